// round 10
// baseline (speedup 1.0000x reference)
#include <cuda_runtime.h>

#define B_TOTAL 16384
#define NSTEPS  196

typedef unsigned long long u64;

// Scratch (allocation-free: __device__ globals)
__device__ float g_xT[784 * B_TOTAL];    // transposed, PRE-HALVED input: [pixel][batch] = 0.5*x
__device__ float g_w1T[NSTEPS * 4 * 20]; // fc1 weights relaid: [(s*4+w)*20 + o]

// ---------------------------------------------------------------------------
// f32x2 packed helpers. Lanes = two adjacent basis amplitudes (2g, 2g+1).
// UPK is free (register-pair halves); PK/BC cost ALU MOVs (overlap fma pipe).
// ---------------------------------------------------------------------------
__device__ __forceinline__ u64 PK(float lo, float hi) {
    u64 r; asm("mov.b64 %0,{%1,%2};" : "=l"(r) : "f"(lo), "f"(hi)); return r;
}
__device__ __forceinline__ void UPK(u64 v, float& lo, float& hi) {
    asm("mov.b64 {%0,%1},%2;" : "=f"(lo), "=f"(hi) : "l"(v));
}
__device__ __forceinline__ u64 BC(float x) { return PK(x, x); }
__device__ __forceinline__ u64 F2FMA(u64 a, u64 b, u64 c) {
    u64 d; asm("fma.rn.f32x2 %0,%1,%2,%3;" : "=l"(d) : "l"(a), "l"(b), "l"(c)); return d;
}
__device__ __forceinline__ u64 F2MUL(u64 a, u64 b) {
    u64 d; asm("mul.rn.f32x2 %0,%1,%2;" : "=l"(d) : "l"(a), "l"(b)); return d;
}
__device__ __forceinline__ u64 F2ADD(u64 a, u64 b) {
    u64 d; asm("add.rn.f32x2 %0,%1,%2;" : "=l"(d) : "l"(a), "l"(b)); return d;
}
__device__ __forceinline__ u64 F2SUB(u64 a, u64 b) {
    u64 d; asm("sub.rn.f32x2 %0,%1,%2;" : "=l"(d) : "l"(a), "l"(b)); return d;
}
__device__ __forceinline__ float HADD(u64 v) { float l, h; UPK(v, l, h); return l + h; }
__device__ __forceinline__ float HSUB(u64 v) { float l, h; UPK(v, l, h); return l - h; }

// ---------------------------------------------------------------------------
// Prep kernel: float4 transpose of x (B,784) -> g_xT[p][b] = 0.5*x[b][p],
// plus fc1_w relayout (blocks with blockIdx.y == 25)
// ---------------------------------------------------------------------------
__global__ void prep_kernel(const float* __restrict__ x, const float* __restrict__ fc1_w) {
    if (blockIdx.y == 25) {
        int t = threadIdx.y * 8 + threadIdx.x;
        int idx = blockIdx.x * 256 + t;
        if (idx < 784 * 20) {
            int p = idx / 20, o = idx % 20;
            g_w1T[idx] = fc1_w[o * 784 + p];
        }
        return;
    }
    __shared__ float tile[32][33];
    const int bBase = blockIdx.x * 32;
    const int pBase = blockIdx.y * 32;
    const int tx = threadIdx.x, ty = threadIdx.y;
    int p0 = pBase + tx * 4;
    float4 v = make_float4(0.f, 0.f, 0.f, 0.f);
    if (p0 < 784) v = *(const float4*)(x + (bBase + ty) * 784 + p0);
    tile[tx * 4 + 0][ty] = 0.5f * v.x;
    tile[tx * 4 + 1][ty] = 0.5f * v.y;
    tile[tx * 4 + 2][ty] = 0.5f * v.z;
    tile[tx * 4 + 3][ty] = 0.5f * v.w;
    __syncthreads();
    int p = pBase + ty;
    if (p < 784) {
        float4 w = make_float4(tile[ty][tx * 4 + 0], tile[ty][tx * 4 + 1],
                               tile[ty][tx * 4 + 2], tile[ty][tx * 4 + 3]);
        *(float4*)(g_xT + p * B_TOTAL + bBase + tx * 4) = w;
    }
}

// ---------------------------------------------------------------------------
// Packed butterflies, wires 0..2 (packed stride S in {4,2,1}); coefficients
// broadcast to both lanes. U = [[u,v],[v*,-u*]].
// ---------------------------------------------------------------------------
template<int S>
__device__ __forceinline__ void applyP(u64* Sr2, u64* Si2,
    float ur, float ui, float vr, float vi)
{
    u64 Bur = BC(ur), Bui = BC(ui), Bvr = BC(vr), Bvi = BC(vi);
    u64 Bnur = BC(-ur), Bnui = BC(-ui), Bnvi = BC(-vi);
    #pragma unroll
    for (int g = 0; g < 4; g++) {
        int i0 = ((g & ~(S - 1)) << 1) | (g & (S - 1));
        int i1 = i0 + S;
        u64 X0r = Sr2[i0], X0i = Si2[i0], X1r = Sr2[i1], X1i = Si2[i1];
        u64 Y0r = F2FMA(Bnvi, X1i, F2FMA(Bvr,  X1r, F2FMA(Bnui, X0i, F2MUL(Bur, X0r))));
        u64 Y0i = F2FMA(Bvi,  X1r, F2FMA(Bvr,  X1i, F2FMA(Bui,  X0r, F2MUL(Bur, X0i))));
        u64 Y1r = F2FMA(Bnui, X1i, F2FMA(Bnur, X1r, F2FMA(Bvi,  X0i, F2MUL(Bvr, X0r))));
        u64 Y1i = F2FMA(Bui,  X1r, F2FMA(Bnur, X1i, F2FMA(Bnvi, X0r, F2MUL(Bvr, X0i))));
        Sr2[i0] = Y0r; Si2[i0] = Y0i; Sr2[i1] = Y1r; Si2[i1] = Y1i;
    }
}

// Wire 3: butterfly WITHIN each packed register (lanes are the pair).
// y_lo = u x_lo + v x_hi ; y_hi = v* x_lo - u* x_hi, via lane-swapped operands
// and sign-packed constants (verified lane-by-lane).
__device__ __forceinline__ void applyW3(u64* Sr2, u64* Si2,
    float ur, float ui, float vr, float vi)
{
    u64 A2  = PK(ur, -ur);
    u64 Bn2 = BC(-ui), Bp2 = BC(ui);
    u64 C2  = BC(vr);
    u64 D2  = PK(-vi, vi), Dp2 = PK(vi, -vi);
    #pragma unroll
    for (int g = 0; g < 8; g++) {
        u64 Xr = Sr2[g], Xi = Si2[g];
        float lr, hr, li, hi_;
        UPK(Xr, lr, hr); UPK(Xi, li, hi_);
        u64 Xsr = PK(hr, lr), Xsi = PK(hi_, li);
        u64 Yr = F2FMA(D2,  Xsi, F2FMA(C2, Xsr, F2FMA(Bn2, Xi, F2MUL(A2, Xr))));
        u64 Yi = F2FMA(Dp2, Xsr, F2FMA(C2, Xsi, F2FMA(Bp2, Xr, F2MUL(A2, Xi))));
        Sr2[g] = Yr; Si2[g] = Yi;
    }
}

// ---------------------------------------------------------------------------
// Main kernel: one thread per batch element; state packed as 8+8 u64
// (lane pairing on the lowest amplitude bit = wire 3).
// ---------------------------------------------------------------------------
__global__ __launch_bounds__(128, 1) void quanv_kernel(
    const float* __restrict__ crz_p, const float* __restrict__ ry_p,
    const float* __restrict__ fc1_b, const float* __restrict__ fc2_w,
    const float* __restrict__ fc2_b, float* __restrict__ out)
{
    const int b = blockIdx.x * 128 + threadIdx.x;
    const float RS = 0.7071067811865476f;

    // CRZ packed diagonal: sgn table {0,-1,-1,0,-1,-2,0,1,-1,0,-2,1,0,1,1,4}
    // paired (2g,2g+1); phase = exp(+0.5 i theta sgn) -> (cos, sin)
    const float th = __ldg(crz_p);
    const float c1 = __cosf(0.5f * th), s1 = __sinf(0.5f * th);
    const float c2 = __cosf(th),        s2 = __sinf(th);
    const float c4 = __cosf(2.0f * th), s4 = __sinf(2.0f * th);
    u64 Dr2[8], Di2[8];
    Dr2[0] = PK(1.f, c1);  Di2[0] = PK(0.f, -s1);
    Dr2[1] = PK(c1, 1.f);  Di2[1] = PK(-s1, 0.f);
    Dr2[2] = PK(c1, c2);   Di2[2] = PK(-s1, -s2);
    Dr2[3] = PK(1.f, c1);  Di2[3] = PK(0.f, s1);
    Dr2[4] = PK(c1, 1.f);  Di2[4] = PK(-s1, 0.f);
    Dr2[5] = PK(c2, c1);   Di2[5] = PK(-s2, s1);
    Dr2[6] = PK(1.f, c1);  Di2[6] = PK(0.f, s1);
    Dr2[7] = PK(c1, c4);   Di2[7] = PK(s1, s4);

    const float ryt = __ldg(ry_p);
    const float cTH  = __cosf(ryt);
    const float s2TH = 2.0f * __sinf(ryt);
    const float chh = __cosf(0.5f * ryt), shh = __sinf(0.5f * ryt);
    const float gAf = RS * (chh + shh), gBf = RS * (chh - shh);  // H*Ry entries
    float gA = RS, gB = RS;  // step 0: plain H

    // State |0000>, packed pairs
    u64 Sr2[8], Si2[8];
    #pragma unroll
    for (int n = 0; n < 8; n++) { Sr2[n] = PK(0.f, 0.f); Si2[n] = PK(0.f, 0.f); }
    Sr2[0] = PK(1.f, 0.f);

    // Fused fc1 accumulators, packed (10 pairs)
    u64 h2[10];
    #pragma unroll
    for (int k = 0; k < 10; k++) h2[k] = PK(__ldg(&fc1_b[2 * k]), __ldg(&fc1_b[2 * k + 1]));

    // Prefetch step-0 angles (pre-halved)
    float A[16];
    #pragma unroll
    for (int k = 0; k < 16; k++) {
        int r = k >> 2, c = k & 3;
        A[k] = g_xT[(r * 28 + c) * B_TOTAL + b];
    }

    int wi = 0, wj = 0;
    #pragma unroll 1
    for (int s = 0; s < NSTEPS; s++) {
        // ---- prefetch next step's 16 (half-)angles ----
        float An[16];
        {
            int nwj = wj + 1, nwi = wi;
            if (nwj == 14) { nwj = 0; nwi++; }
            bool valid = (s + 1 < NSTEPS);
            int i2 = 2 * nwi, j2 = 2 * nwj;
            int hh = (i2 == 26) ? 2 : 4;
            int ww = (j2 == 26) ? 2 : 4;
            int hw = hh * ww;
            #pragma unroll
            for (int k = 0; k < 16; k++) {
                float v = 0.f;
                if (valid && k < hw) {
                    int r, c;
                    if (ww == 4) { r = k >> 2; c = k & 3; }
                    else         { r = k >> 1; c = k & 1; }
                    v = g_xT[((i2 + r) * 28 + (j2 + c)) * B_TOTAL + b];
                }
                An[k] = v;
            }
        }

        // ---- build all 4 gates (scalar quaternion chains) ----
        float Ur[4], Ui[4], Vr[4], Vi[4];
        #pragma unroll
        for (int w = 0; w < 3; w++) {
            float c0a = __cosf(A[w*5+0]), s0a = __sinf(A[w*5+0]);
            float c1a = __cosf(A[w*5+1]), s1a = __sinf(A[w*5+1]);
            float c2a = __cosf(A[w*5+2]), s2a = __sinf(A[w*5+2]);
            float c3a = __cosf(A[w*5+3]), s3a = __sinf(A[w*5+3]);
            float c4a = __cosf(A[w*5+4]), s4a = __sinf(A[w*5+4]);
            float qw = c4a * c3a, qx = -s4a * s3a, qy = c4a * s3a, qz = s4a * c3a;
            float tw = qw * c2a - qz * s2a;
            float tx = qx * c2a + qy * s2a;
            float ty = qy * c2a - qx * s2a;
            float tz = qz * c2a + qw * s2a;
            qw = tw * c1a - ty * s1a;
            qx = tx * c1a - tz * s1a;
            qy = ty * c1a + tw * s1a;
            qz = tz * c1a + tx * s1a;
            tw = qw * c0a - qz * s0a;
            tx = qx * c0a + qy * s0a;
            ty = qy * c0a - qx * s0a;
            tz = qz * c0a + qw * s0a;
            float P = tw * gA - ty * gB;
            float Q = tz * gA + tx * gB;
            float R = tw * gB + ty * gA;
            float T = tx * gA - tz * gB;
            Ur[w] = P; Ui[w] = -Q; Vr[w] = R; Vi[w] = T;
        }
        {   // wire 3: U = Rz(a15) * G
            float c0a = __cosf(A[15]), s0a = __sinf(A[15]);
            Ur[3] = c0a * gA; Ui[3] = -s0a * gA;
            Vr[3] = c0a * gB; Vi[3] = -s0a * gB;
        }

        // ---- apply gates (packed strides 4,2,1 then in-register wire 3) ----
        applyP<4>(Sr2, Si2, Ur[0], Ui[0], Vr[0], Vi[0]);
        applyP<2>(Sr2, Si2, Ur[1], Ui[1], Vr[1], Vi[1]);
        applyP<1>(Sr2, Si2, Ur[2], Ui[2], Vr[2], Vi[2]);
        applyW3(Sr2, Si2, Ur[3], Ui[3], Vr[3], Vi[3]);

        // ---- packed probs + Z tree (before CRZ; CRZ-invariant) ----
        u64 p2[8];
        #pragma unroll
        for (int g = 0; g < 8; g++)
            p2[g] = F2FMA(Si2[g], Si2[g], F2MUL(Sr2[g], Sr2[g]));
        u64 q01 = F2ADD(p2[0], p2[1]), q23 = F2ADD(p2[2], p2[3]);
        u64 q45 = F2ADD(p2[4], p2[5]), q67 = F2ADD(p2[6], p2[7]);
        u64 s03 = F2ADD(q01, q23), s47 = F2ADD(q45, q67);
        float z3 = HSUB(F2ADD(s03, s47));
        float z0 = HADD(F2SUB(s03, s47));
        float z1 = HADD(F2SUB(F2ADD(q01, q45), F2ADD(q23, q67)));
        u64 Ev = F2ADD(F2ADD(p2[0], p2[2]), F2ADD(p2[4], p2[6]));
        u64 Ov = F2ADD(F2ADD(p2[1], p2[3]), F2ADD(p2[5], p2[7]));
        float z2 = HADD(F2SUB(Ev, Ov));

        // ---- CRZ diagonal (packed complex scale) ----
        #pragma unroll
        for (int g = 0; g < 8; g++) {
            u64 nr = F2SUB(F2MUL(Sr2[g], Dr2[g]), F2MUL(Si2[g], Di2[g]));
            u64 ni = F2FMA(Sr2[g], Di2[g], F2MUL(Si2[g], Dr2[g]));
            Sr2[g] = nr; Si2[g] = ni;
        }

        // ---- X expectations (packed dots; x3 scalar within-lane) ----
        u64 a0 = F2MUL(Sr2[0], Sr2[4]);
        a0 = F2FMA(Si2[0], Si2[4], a0); a0 = F2FMA(Sr2[1], Sr2[5], a0);
        a0 = F2FMA(Si2[1], Si2[5], a0); a0 = F2FMA(Sr2[2], Sr2[6], a0);
        a0 = F2FMA(Si2[2], Si2[6], a0); a0 = F2FMA(Sr2[3], Sr2[7], a0);
        a0 = F2FMA(Si2[3], Si2[7], a0);
        float x0 = HADD(a0);
        u64 a1 = F2MUL(Sr2[0], Sr2[2]);
        a1 = F2FMA(Si2[0], Si2[2], a1); a1 = F2FMA(Sr2[1], Sr2[3], a1);
        a1 = F2FMA(Si2[1], Si2[3], a1); a1 = F2FMA(Sr2[4], Sr2[6], a1);
        a1 = F2FMA(Si2[4], Si2[6], a1); a1 = F2FMA(Sr2[5], Sr2[7], a1);
        a1 = F2FMA(Si2[5], Si2[7], a1);
        float x1 = HADD(a1);
        u64 a2 = F2MUL(Sr2[0], Sr2[1]);
        a2 = F2FMA(Si2[0], Si2[1], a2); a2 = F2FMA(Sr2[2], Sr2[3], a2);
        a2 = F2FMA(Si2[2], Si2[3], a2); a2 = F2FMA(Sr2[4], Sr2[5], a2);
        a2 = F2FMA(Si2[4], Si2[5], a2); a2 = F2FMA(Sr2[6], Sr2[7], a2);
        a2 = F2FMA(Si2[6], Si2[7], a2);
        float x2 = HADD(a2);
        float x3 = 0.f;
        #pragma unroll
        for (int g = 0; g < 8; g++) {
            float lr, hr, li, hi_;
            UPK(Sr2[g], lr, hr); UPK(Si2[g], li, hi_);
            x3 = fmaf(lr, hr, x3);
            x3 = fmaf(li, hi_, x3);
        }

        float e0 = cTH * z0 - s2TH * x0;
        float e1 = cTH * z1 - s2TH * x1;
        float e2 = cTH * z2 - s2TH * x2;
        float e3 = cTH * z3 - s2TH * x3;

        // ---- fused fc1 (packed accumulators, 128-bit weight loads) ----
        {
            const ulonglong2* w2 = (const ulonglong2*)(g_w1T + s * 80);
            float ev[4] = {e0, e1, e2, e3};
            #pragma unroll
            for (int w = 0; w < 4; w++) {
                u64 Be = BC(ev[w]);
                #pragma unroll
                for (int j = 0; j < 5; j++) {
                    ulonglong2 ww = __ldg(&w2[w * 5 + j]);
                    h2[2 * j + 0] = F2FMA(Be, ww.x, h2[2 * j + 0]);
                    h2[2 * j + 1] = F2FMA(Be, ww.y, h2[2 * j + 1]);
                }
            }
        }

        // rotate prefetched angles in; switch G to H*Ry after first step
        #pragma unroll
        for (int k = 0; k < 16; k++) A[k] = An[k];
        gA = gAf; gB = gBf;
        wj++; if (wj == 14) { wj = 0; wi++; }
    }

    // ---- leaky relu + fc2 ----
    float o0 = __ldg(&fc2_b[0]), o1 = __ldg(&fc2_b[1]);
    #pragma unroll
    for (int k = 0; k < 10; k++) {
        float hlo, hhi; UPK(h2[k], hlo, hhi);
        float ha = (hlo > 0.f) ? hlo : 0.1f * hlo;
        float hb = (hhi > 0.f) ? hhi : 0.1f * hhi;
        o0 += ha * __ldg(&fc2_w[2 * k])     + hb * __ldg(&fc2_w[2 * k + 1]);
        o1 += ha * __ldg(&fc2_w[20 + 2 * k]) + hb * __ldg(&fc2_w[21 + 2 * k]);
    }
    out[b * 2 + 0] = o0;
    out[b * 2 + 1] = o1;
}

// ---------------------------------------------------------------------------
// Launch
// ---------------------------------------------------------------------------
extern "C" void kernel_launch(void* const* d_in, const int* in_sizes, int n_in,
                              void* d_out, int out_size) {
    const float* x      = (const float*)d_in[0];
    const float* crz_t  = (const float*)d_in[1];
    const float* ry_t   = (const float*)d_in[2];
    const float* fc1_w  = (const float*)d_in[3];
    const float* fc1_b  = (const float*)d_in[4];
    const float* fc2_w  = (const float*)d_in[5];
    const float* fc2_b  = (const float*)d_in[6];
    float* out = (float*)d_out;

    dim3 tbP(8, 32);
    dim3 tgP(B_TOTAL / 32, 26);
    prep_kernel<<<tgP, tbP>>>(x, fc1_w);

    quanv_kernel<<<B_TOTAL / 128, 128>>>(crz_t, ry_t, fc1_b, fc2_w, fc2_b, out);
}

// round 12
// speedup vs baseline: 1.0004x; 1.0004x over previous
#include <cuda_runtime.h>

#define B_TOTAL 16384
#define NSTEPS  196

// Scratch (allocation-free: __device__ globals)
__device__ float g_xT[784 * B_TOTAL];   // transposed, PRE-HALVED input: [pixel][batch]
__device__ float g_w1S[NSTEPS * 80];    // fc1 weights split: [s][p][w][j]  (p=lane parity, j=0..9)

// ---------------------------------------------------------------------------
// Prep kernel: float4 transpose of x -> g_xT = 0.5*x^T, plus fc1_w relayout.
// ---------------------------------------------------------------------------
__global__ void prep_kernel(const float* __restrict__ x, const float* __restrict__ fc1_w) {
    if (blockIdx.y == 25) {
        int t = threadIdx.y * 8 + threadIdx.x;
        int idx = blockIdx.x * 256 + t;
        if (idx < 784 * 20) {
            int col = idx / 20, o = idx % 20;
            int s = col >> 2, w = col & 3;
            int p = o / 10, j = o % 10;
            g_w1S[s * 80 + p * 40 + w * 10 + j] = fc1_w[o * 784 + col];
        }
        return;
    }
    __shared__ float tile[32][33];
    const int bBase = blockIdx.x * 32;
    const int pBase = blockIdx.y * 32;
    const int tx = threadIdx.x, ty = threadIdx.y;
    int p0 = pBase + tx * 4;
    float4 v = make_float4(0.f, 0.f, 0.f, 0.f);
    if (p0 < 784) v = *(const float4*)(x + (bBase + ty) * 784 + p0);
    tile[tx * 4 + 0][ty] = 0.5f * v.x;
    tile[tx * 4 + 1][ty] = 0.5f * v.y;
    tile[tx * 4 + 2][ty] = 0.5f * v.z;
    tile[tx * 4 + 3][ty] = 0.5f * v.w;
    __syncthreads();
    int p = pBase + ty;
    if (p < 784) {
        float4 w = make_float4(tile[ty][tx * 4 + 0], tile[ty][tx * 4 + 1],
                               tile[ty][tx * 4 + 2], tile[ty][tx * 4 + 3]);
        *(float4*)(g_xT + p * B_TOTAL + bBase + tx * 4) = w;
    }
}

// ---------------------------------------------------------------------------
// Local apply (m-space, 8 amplitudes, stride S in {4,2,1}):
// U = [[u,v],[v*,-u*]], 4 butterflies, 16 FFMA each.
// ---------------------------------------------------------------------------
template<int S>
__device__ __forceinline__ void applyL(float* Sr, float* Si,
    float ur, float ui, float vr, float vi)
{
    #pragma unroll
    for (int g = 0; g < 4; g++) {
        int i0 = ((g & ~(S - 1)) << 1) | (g & (S - 1));
        int i1 = i0 + S;
        float x0r = Sr[i0], x0i = Si[i0], x1r = Sr[i1], x1i = Si[i1];
        Sr[i0] = ur * x0r - ui * x0i + vr * x1r - vi * x1i;
        Si[i0] = ur * x0i + ui * x0r + vr * x1i + vi * x1r;
        Sr[i1] = vr * x0r + vi * x0i - ur * x1r - ui * x1i;
        Si[i1] = vr * x0i - vi * x0r - ur * x1i + ui * x1r;
    }
}

// Quaternion chain: RZ(a4)RY(a3)RZ(a2)RY(a1)RZ(a0) * G,  G=[gA,gB;gB,-gA].
// Returns u,v of [[u,v],[v*,-u*]].
__device__ __forceinline__ void chain5(const float* a, float gA, float gB,
    float& ur, float& ui, float& vr, float& vi)
{
    float c0a = __cosf(a[0]), s0a = __sinf(a[0]);
    float c1a = __cosf(a[1]), s1a = __sinf(a[1]);
    float c2a = __cosf(a[2]), s2a = __sinf(a[2]);
    float c3a = __cosf(a[3]), s3a = __sinf(a[3]);
    float c4a = __cosf(a[4]), s4a = __sinf(a[4]);
    float qw = c4a * c3a, qx = -s4a * s3a, qy = c4a * s3a, qz = s4a * c3a;
    float tw = qw * c2a - qz * s2a;
    float tx = qx * c2a + qy * s2a;
    float ty = qy * c2a - qx * s2a;
    float tz = qz * c2a + qw * s2a;
    qw = tw * c1a - ty * s1a;
    qx = tx * c1a - tz * s1a;
    qy = ty * c1a + tw * s1a;
    qz = tz * c1a + tx * s1a;
    tw = qw * c0a - qz * s0a;
    tx = qx * c0a + qy * s0a;
    ty = qy * c0a - qx * s0a;
    tz = qz * c0a + qw * s0a;
    ur = tw * gA - ty * gB;
    ui = -(tz * gA + tx * gB);
    vr = tw * gB + ty * gA;
    vi = tx * gA - tz * gB;
}

// ---------------------------------------------------------------------------
// Main kernel: TWO lanes per batch element (lane^16 partners).
// Lane parity p = lane>>4 holds the 8 amplitudes with wire-0 bit == p.
// ---------------------------------------------------------------------------
__global__ __launch_bounds__(256, 1) void quanv_kernel(
    const float* __restrict__ crz_p, const float* __restrict__ ry_p,
    const float* __restrict__ fc1_b, const float* __restrict__ fc2_w,
    const float* __restrict__ fc2_b, float* __restrict__ out)
{
    const unsigned FULL = 0xffffffffu;
    const int lane = threadIdx.x & 31;
    const int p    = lane >> 4;                      // parity 0/1
    const float psgn = p ? -1.f : 1.f;
    const int e = blockIdx.x * 128 + (threadIdx.x >> 5) * 16 + (lane & 15);
    const int srcLo = lane & 15;                     // pair's p0 lane
    const int srcHi = lane | 16;                     // pair's p1 lane
    const int p10 = p * 10;
    const float RS = 0.7071067811865476f;

    // CRZ per-parity phase table: full sgn {0,-1,-1,0,-1,-2,0,1,-1,0,-2,1,0,1,1,4}
    const float th = __ldg(crz_p);
    const float c1 = __cosf(0.5f * th), s1 = __sinf(0.5f * th);
    const float c2 = __cosf(th),        s2 = __sinf(th);
    const float c4 = __cosf(2.0f * th), s4 = __sinf(2.0f * th);
    float crzr[8], crzi[8];
    // p0 (n=0..7):   (1,0)(c1,-s1)(c1,-s1)(1,0)(c1,-s1)(c2,-s2)(1,0)(c1,s1)
    // p1 (n=8..15):  (c1,-s1)(1,0)(c2,-s2)(c1,s1)(1,0)(c1,s1)(c1,s1)(c4,s4)
    crzr[0] = p ? c1 : 1.f;  crzi[0] = p ? -s1 : 0.f;
    crzr[1] = p ? 1.f : c1;  crzi[1] = p ? 0.f : -s1;
    crzr[2] = p ? c2 : c1;   crzi[2] = p ? -s2 : -s1;
    crzr[3] = p ? c1 : 1.f;  crzi[3] = p ? s1 : 0.f;
    crzr[4] = p ? 1.f : c1;  crzi[4] = p ? 0.f : -s1;
    crzr[5] = p ? c1 : c2;   crzi[5] = p ? s1 : -s2;
    crzr[6] = p ? c1 : 1.f;  crzi[6] = p ? s1 : 0.f;
    crzr[7] = p ? c4 : c1;   crzi[7] = p ? s4 : s1;

    const float ryt = __ldg(ry_p);
    const float cTH  = __cosf(ryt);
    const float s2TH = 2.0f * __sinf(ryt);
    const float chh = __cosf(0.5f * ryt), shh = __sinf(0.5f * ryt);
    const float gAf = RS * (chh + shh), gBf = RS * (chh - shh);
    float gA = RS, gB = RS;   // step 0: plain H

    // Local 8 amplitudes (m-space); |0000> -> p0 has amp m=0 == 1
    float Sr[8], Si[8];
    #pragma unroll
    for (int m = 0; m < 8; m++) { Sr[m] = 0.f; Si[m] = 0.f; }
    Sr[0] = p ? 0.f : 1.f;

    // fc1 accumulators: this lane owns outputs o = p*10 + (0..9)
    float h[10];
    #pragma unroll
    for (int j = 0; j < 10; j++) h[j] = __ldg(&fc1_b[p10 + j]);

    // Prefetch step-0 angles: this lane needs global k = p*10 + kk, kk<10
    float A[10];
    #pragma unroll
    for (int kk = 0; kk < 10; kk++) {
        int k = p10 + kk;
        float v = 0.f;
        if (k < 16) {
            int r = k >> 2, c = k & 3;
            v = g_xT[(r * 28 + c) * B_TOTAL + e];
        }
        A[kk] = v;
    }

    int wi = 0, wj = 0;
    #pragma unroll 1
    for (int s = 0; s < NSTEPS; s++) {
        // ---- prefetch next step's angles (this lane's 10) ----
        float An[10];
        {
            int nwj = wj + 1, nwi = wi;
            if (nwj == 14) { nwj = 0; nwi++; }
            bool valid = (s + 1 < NSTEPS);
            int i2 = 2 * nwi, j2 = 2 * nwj;
            int hh = (i2 == 26) ? 2 : 4;
            int ww = (j2 == 26) ? 2 : 4;
            int hw = hh * ww;
            int base = i2 * 28 + j2;
            #pragma unroll
            for (int kk = 0; kk < 10; kk++) {
                int k = p10 + kk;
                float v = 0.f;
                if (valid && k < hw) {
                    int r, c;
                    if (ww == 4) { r = k >> 2; c = k & 3; }
                    else         { r = k >> 1; c = k & 1; }
                    v = g_xT[(base + r * 28 + c) * B_TOTAL + e];
                }
                An[kk] = v;
            }
        }

        // ---- build this lane's 2 gate chains (uniform code, no divergence)
        //      p0: chains for wires 0,1 ; p1: chains for wires 2,3
        //      (wire 3 = 5-angle chain with a1..a4 == 0)
        float o1u_r, o1u_i, o1v_r, o1v_i;
        float o2u_r, o2u_i, o2v_r, o2v_i;
        chain5(A,     gA, gB, o1u_r, o1u_i, o1v_r, o1v_i);
        chain5(A + 5, gA, gB, o2u_r, o2u_i, o2v_r, o2v_i);

        // ---- distribute gates: U_w for w=0..3 via src-lane shfl ----
        float U0r = __shfl_sync(FULL, o1u_r, srcLo);
        float U0i = __shfl_sync(FULL, o1u_i, srcLo);
        float V0r = __shfl_sync(FULL, o1v_r, srcLo);
        float V0i = __shfl_sync(FULL, o1v_i, srcLo);
        float U1r = __shfl_sync(FULL, o2u_r, srcLo);
        float U1i = __shfl_sync(FULL, o2u_i, srcLo);
        float V1r = __shfl_sync(FULL, o2v_r, srcLo);
        float V1i = __shfl_sync(FULL, o2v_i, srcLo);
        float U2r = __shfl_sync(FULL, o1u_r, srcHi);
        float U2i = __shfl_sync(FULL, o1u_i, srcHi);
        float V2r = __shfl_sync(FULL, o1v_r, srcHi);
        float V2i = __shfl_sync(FULL, o1v_i, srcHi);
        float U3r = __shfl_sync(FULL, o2u_r, srcHi);
        float U3i = __shfl_sync(FULL, o2u_i, srcHi);
        float V3r = __shfl_sync(FULL, o2v_r, srcHi);
        float V3i = __shfl_sync(FULL, o2v_i, srcHi);

        // ---- local applies: wires 1,2,3 (m-space strides 4,2,1) ----
        applyL<4>(Sr, Si, U1r, U1i, V1r, V1i);
        applyL<2>(Sr, Si, U2r, U2i, V2r, V2i);
        applyL<1>(Sr, Si, U3r, U3i, V3r, V3i);

        // ---- wire 0: cross-lane butterfly ----
        // p0: y = u*loc + v*part ; p1: y = -conj(u)*loc + conj(v)*part
        {
            float ar = psgn * U0r, ai = U0i;
            float br = V0r,        bi = psgn * V0i;
            float Pr[8], Pi[8];
            #pragma unroll
            for (int m = 0; m < 8; m++) {
                Pr[m] = __shfl_xor_sync(FULL, Sr[m], 16);
                Pi[m] = __shfl_xor_sync(FULL, Si[m], 16);
            }
            #pragma unroll
            for (int m = 0; m < 8; m++) {
                float lr = Sr[m], li = Si[m];
                Sr[m] = ar * lr - ai * li + br * Pr[m] - bi * Pi[m];
                Si[m] = ar * li + ai * lr + br * Pi[m] + bi * Pr[m];
            }
        }

        // ---- probs + Z partials (pre-CRZ; CRZ-invariant) ----
        float pm[8];
        #pragma unroll
        for (int m = 0; m < 8; m++) pm[m] = Sr[m] * Sr[m] + Si[m] * Si[m];
        float s01 = pm[0] + pm[1], s23 = pm[2] + pm[3];
        float s45 = pm[4] + pm[5], s67 = pm[6] + pm[7];
        float z0pp = psgn * (s01 + s23 + s45 + s67);
        float z1pp = (s01 + s23) - (s45 + s67);
        float z2pp = (s01 + s45) - (s23 + s67);
        float z3pp = (pm[0] + pm[2] + pm[4] + pm[6]) - (pm[1] + pm[3] + pm[5] + pm[7]);
        float z0 = z0pp + __shfl_xor_sync(FULL, z0pp, 16);
        float z1 = z1pp + __shfl_xor_sync(FULL, z1pp, 16);
        float z2 = z2pp + __shfl_xor_sync(FULL, z2pp, 16);
        float z3 = z3pp + __shfl_xor_sync(FULL, z3pp, 16);

        // ---- CRZ diagonal (per-parity constants) ----
        #pragma unroll
        for (int m = 0; m < 8; m++) {
            float r_ = Sr[m] * crzr[m] - Si[m] * crzi[m];
            Si[m]    = Sr[m] * crzi[m] + Si[m] * crzr[m];
            Sr[m]    = r_;
        }

        // ---- X expectations ----
        float x1pp = Sr[0]*Sr[4] + Si[0]*Si[4] + Sr[1]*Sr[5] + Si[1]*Si[5]
                   + Sr[2]*Sr[6] + Si[2]*Si[6] + Sr[3]*Sr[7] + Si[3]*Si[7];
        float x2pp = Sr[0]*Sr[2] + Si[0]*Si[2] + Sr[1]*Sr[3] + Si[1]*Si[3]
                   + Sr[4]*Sr[6] + Si[4]*Si[6] + Sr[5]*Sr[7] + Si[5]*Si[7];
        float x3pp = Sr[0]*Sr[1] + Si[0]*Si[1] + Sr[2]*Sr[3] + Si[2]*Si[3]
                   + Sr[4]*Sr[5] + Si[4]*Si[5] + Sr[6]*Sr[7] + Si[6]*Si[7];
        float x1 = x1pp + __shfl_xor_sync(FULL, x1pp, 16);
        float x2 = x2pp + __shfl_xor_sync(FULL, x2pp, 16);
        float x3 = x3pp + __shfl_xor_sync(FULL, x3pp, 16);
        float x0 = 0.f;
        #pragma unroll
        for (int m = 0; m < 8; m++) {
            float pr = __shfl_xor_sync(FULL, Sr[m], 16);
            float pi = __shfl_xor_sync(FULL, Si[m], 16);
            x0 = fmaf(Sr[m], pr, x0);
            x0 = fmaf(Si[m], pi, x0);
        }
        // x0 partial products are symmetric across the pair -> already the full sum

        float ev[4];
        ev[0] = cTH * z0 - s2TH * x0;
        ev[1] = cTH * z1 - s2TH * x1;
        ev[2] = cTH * z2 - s2TH * x2;
        ev[3] = cTH * z3 - s2TH * x3;

        // ---- fused fc1: this lane's 10 outputs, 40 weights (10x float4) ----
        {
            const float4* wv = (const float4*)(g_w1S + s * 80 + p * 40);
            #pragma unroll
            for (int q = 0; q < 10; q++) {
                float4 ww = __ldg(&wv[q]);
                h[(4*q + 0) % 10] = fmaf(ev[(4*q + 0) / 10], ww.x, h[(4*q + 0) % 10]);
                h[(4*q + 1) % 10] = fmaf(ev[(4*q + 1) / 10], ww.y, h[(4*q + 1) % 10]);
                h[(4*q + 2) % 10] = fmaf(ev[(4*q + 2) / 10], ww.z, h[(4*q + 2) % 10]);
                h[(4*q + 3) % 10] = fmaf(ev[(4*q + 3) / 10], ww.w, h[(4*q + 3) % 10]);
            }
        }

        // rotate angles in; switch G to H*Ry after first step
        #pragma unroll
        for (int kk = 0; kk < 10; kk++) A[kk] = An[kk];
        gA = gAf; gB = gBf;
        wj++; if (wj == 14) { wj = 0; wi++; }
    }

    // ---- leaky relu + fc2 (split over the pair, then bfly-add) ----
    float o0p = 0.f, o1p = 0.f;
    #pragma unroll
    for (int j = 0; j < 10; j++) {
        float hv = h[j];
        hv = (hv > 0.f) ? hv : 0.1f * hv;
        o0p += hv * __ldg(&fc2_w[p10 + j]);
        o1p += hv * __ldg(&fc2_w[20 + p10 + j]);
    }
    float o0 = o0p + __shfl_xor_sync(FULL, o0p, 16);
    float o1 = o1p + __shfl_xor_sync(FULL, o1p, 16);
    if (p == 0) {
        ((float2*)out)[e] = make_float2(o0 + __ldg(&fc2_b[0]), o1 + __ldg(&fc2_b[1]));
    }
}

// ---------------------------------------------------------------------------
// Launch
// ---------------------------------------------------------------------------
extern "C" void kernel_launch(void* const* d_in, const int* in_sizes, int n_in,
                              void* d_out, int out_size) {
    const float* x      = (const float*)d_in[0];
    const float* crz_t  = (const float*)d_in[1];
    const float* ry_t   = (const float*)d_in[2];
    const float* fc1_w  = (const float*)d_in[3];
    const float* fc1_b  = (const float*)d_in[4];
    const float* fc2_w  = (const float*)d_in[5];
    const float* fc2_b  = (const float*)d_in[6];
    float* out = (float*)d_out;

    dim3 tbP(8, 32);
    dim3 tgP(B_TOTAL / 32, 26);
    prep_kernel<<<tgP, tbP>>>(x, fc1_w);

    // 2 lanes per element: 32768 threads, 256/block -> 128 blocks (8 warps/SM)
    quanv_kernel<<<B_TOTAL * 2 / 256, 256>>>(crz_t, ry_t, fc1_b, fc2_w, fc2_b, out);
}